// round 5
// baseline (speedup 1.0000x reference)
#include <cuda_runtime.h>
#include <cuda_bf16.h>
#include <cuda_fp16.h>
#include <math.h>
#include <cstdint>

// ---------------- problem constants ----------------
#define BQ   4096
#define NU   100000
#define DIM  128
#define TOPK 5
#define K1   6
#define NSPLIT 4
#define NPS   25000                    // users per split
#define TM 128                         // queries per CTA
#define TN 128                         // users per tile
#define QB (BQ / TM)                   // 32
#define NTILES ((NPS + TN - 1) / TN)   // 196 (last tile: 40 valid, 88 pad)
#define PADROWS (NTILES * TN - NPS)    // 88
#define CAND 8
#define NCAND (NSPLIT * CAND)          // 32
#define SP_U32 65                      // sims pitch in u32
#define NEG_INF (-3.402823466e38f)

// ---------------- device scratch -------------------------------------------
__device__ float    g_ue_n[(size_t)NU * DIM];
__device__ float    g_q_n[(size_t)BQ * DIM];
__device__ uint32_t g_ubsw[(size_t)NSPLIT * NTILES * 8192];   // pre-swizzled f16 tiles
__device__ __half   g_qh[(size_t)BQ * DIM];
__device__ int      g_ci[(size_t)BQ * NCAND];

// ---------------- helpers ---------------------------------------------------
static __device__ __forceinline__ uint32_t smem_u32(const void* p) {
    uint32_t a;
    asm("{ .reg .u64 t; cvta.to.shared.u64 t, %1; cvt.u32.u64 %0, t; }" : "=r"(a) : "l"(p));
    return a;
}
static __device__ __forceinline__ void ldsm_x4(uint32_t addr, uint32_t r[4]) {
    asm volatile("ldmatrix.sync.aligned.m8n8.x4.shared.b16 {%0,%1,%2,%3}, [%4];"
                 : "=r"(r[0]), "=r"(r[1]), "=r"(r[2]), "=r"(r[3]) : "r"(addr));
}
static __device__ __forceinline__ void mma_f16(uint32_t c[2], const uint32_t a[4],
                                               uint32_t b0, uint32_t b1) {
    asm volatile("mma.sync.aligned.m16n8k16.row.col.f16.f16.f16.f16 "
                 "{%0,%1}, {%2,%3,%4,%5}, {%6,%7}, {%0,%1};"
                 : "+r"(c[0]), "+r"(c[1])
                 : "r"(a[0]), "r"(a[1]), "r"(a[2]), "r"(a[3]), "r"(b0), "r"(b1));
}
static __device__ __forceinline__ void bulk_ld(uint32_t dst, const void* src,
                                               uint32_t bytes, uint32_t mbar) {
    asm volatile("cp.async.bulk.shared::cluster.global.mbarrier::complete_tx::bytes "
                 "[%0], [%1], %2, [%3];"
                 :: "r"(dst), "l"(src), "r"(bytes), "r"(mbar) : "memory");
}
#define MBARRIER_INIT(addr, cnt) \
    asm volatile("mbarrier.init.shared.b64 [%0], %1;" :: "r"((uint32_t)(addr)), "r"((uint32_t)(cnt)) : "memory")
#define MBARRIER_EXPECT_TX(addr, bytes) \
    asm volatile("mbarrier.arrive.expect_tx.shared.b64 _, [%0], %1;" :: "r"((uint32_t)(addr)), "r"((uint32_t)(bytes)) : "memory")
#define MBARRIER_WAIT_PARITY(mbar_addr, parity) do { \
    uint32_t _mbar = (uint32_t)(mbar_addr); \
    uint32_t _par = (uint32_t)(parity); \
    uint32_t _done; \
    asm volatile("{\n\t.reg .pred p;\n\t" \
        "mbarrier.try_wait.parity.acquire.cta.shared::cta.b64 p, [%1], %2;\n\t" \
        "selp.b32 %0, 1, 0, p;\n\t}" : "=r"(_done) : "r"(_mbar), "r"(_par) : "memory"); \
    if (!_done) { \
        asm volatile("{\n\t.reg .pred P1;\n\t" \
            "WAIT_LOOP_%=:\n\t" \
            "mbarrier.try_wait.parity.acquire.cta.shared::cta.b64 P1, [%0], %1, 0x989680;\n\t" \
            "@P1 bra.uni WAIT_DONE_%=;\n\t" \
            "bra.uni WAIT_LOOP_%=;\n\t" \
            "WAIT_DONE_%=:\n\t}" :: "r"(_mbar), "r"(_par) : "memory"); \
    } \
} while (0)
#define FENCE_PROXY_ASYNC() asm volatile("fence.proxy.async.shared::cta;" ::: "memory")

// swizzled byte offset inside a [128 rows x 256B] f16 tile (16B chunks, XOR by row)
static __device__ __forceinline__ uint32_t tile_off(int r, int chunk) {
    return (uint32_t)(r * 256 + ((chunk ^ (r & 7)) << 4));
}

// ---------------- Kernel A: normalize + f16 convert (+ pre-swizzle users) ---
__global__ void prep_kernel(const float* __restrict__ q, const float* __restrict__ u) {
    int row  = blockIdx.x * (blockDim.x >> 5) + (threadIdx.x >> 5);
    int lane = threadIdx.x & 31;
    int total = NU + BQ + NSPLIT * PADROWS;
    if (row >= total) return;

    if (row >= NU + BQ) {
        int pidx = row - (NU + BQ);
        int sp = pidx / PADROWS;
        int r  = (TN - PADROWS) + (pidx % PADROWS);
        size_t base = ((size_t)(sp * NTILES + (NTILES - 1))) << 13;
        uint32_t off = tile_off(r, lane >> 1) >> 2;
        g_ubsw[base + off + (lane & 1) * 2]     = 0u;
        g_ubsw[base + off + (lane & 1) * 2 + 1] = 0u;
        return;
    }

    const float* src;
    if (row < NU) src = u + (size_t)row * DIM;
    else          src = q + (size_t)(row - NU) * DIM;
    float4 v = *(const float4*)(src + lane * 4);
    float s = v.x * v.x + v.y * v.y + v.z * v.z + v.w * v.w;
    #pragma unroll
    for (int o = 16; o > 0; o >>= 1) s += __shfl_xor_sync(0xffffffffu, s, o);
    float inv = 1.0f / fmaxf(sqrtf(s), 1e-12f);
    float4 o4 = make_float4(v.x * inv, v.y * inv, v.z * inv, v.w * inv);

    __half2 h0 = __floats2half2_rn(o4.x, o4.y);
    __half2 h1 = __floats2half2_rn(o4.z, o4.w);
    uint32_t p0 = *(uint32_t*)&h0, p1 = *(uint32_t*)&h1;

    if (row < NU) {
        *(float4*)(g_ue_n + (size_t)row * DIM + lane * 4) = o4;
        int sp = row / NPS, li = row % NPS;
        int tile = li >> 7, r = li & 127;
        size_t base = ((size_t)(sp * NTILES + tile)) << 13;
        uint32_t off = tile_off(r, lane >> 1) >> 2;
        g_ubsw[base + off + (lane & 1) * 2]     = p0;
        g_ubsw[base + off + (lane & 1) * 2 + 1] = p1;
    } else {
        int r = row - NU;
        *(float4*)(g_q_n + (size_t)r * DIM + lane * 4) = o4;
        uint2 pk = make_uint2(p0, p1);
        *(uint2*)(g_qh + (size_t)r * DIM + lane * 4) = pk;
    }
}

// ---------------- Kernel B: f16 HMMA sims + spill/scan top-8 ----------------
// 512 threads, 16 warps, warp tile 32x32 (4 warps per SMSP for latency hiding)
#define OFF_A    0
#define OFF_B0   32768
#define OFF_B1   65536
#define OFF_SIMS 98304
#define OFF_THR  (OFF_SIMS + 128 * SP_U32 * 4)     // 131584
#define OFF_TRIG (OFF_THR + 512)                   // 132096
#define OFF_MBAR (OFF_TRIG + 512)                  // 132608
#define SMEM_BYTES (OFF_MBAR + 64 + 1024)

__global__ __launch_bounds__(512) void cand_kernel() {
    extern __shared__ char sraw[];
    uint32_t sb0 = smem_u32(sraw);
    uint32_t ab = (sb0 + 1023) & ~1023u;
    char* base = sraw + (ab - sb0);

    uint32_t* simsu = (uint32_t*)(base + OFF_SIMS);
    float*    thr   = (float*)(base + OFF_THR);
    int*      trig  = (int*)(base + OFF_TRIG);
    const uint32_t MB = ab + OFF_MBAR;

    const int t = threadIdx.x;
    const int w = t >> 5, lane = t & 31;
    const int wr = w >> 2, wc = w & 3;       // 4x4 warp grid
    const int m0w = wr * 32;
    const int n0w = wc * 32;
    const int q0 = blockIdx.x * TM;
    const int sp = blockIdx.y;
    const int u0 = sp * NPS;

    float topv[CAND]; int topi[CAND];
    #pragma unroll
    for (int p = 0; p < CAND; p++) { topv[p] = NEG_INF; topi[p] = 0; }

    if (t == 0) { MBARRIER_INIT(MB, 1); MBARRIER_INIT(MB + 8, 1); }
    for (int i = t; i < TM; i += 512) { thr[i] = NEG_INF; trig[i] = 0; }

    // load query tile into swizzled smem (once)
    {
        const uint4* src = (const uint4*)(g_qh + (size_t)q0 * DIM);
        for (int i = t; i < TM * 16; i += 512) {
            int r = i >> 4, c = i & 15;
            *(uint4*)(base + OFF_A + tile_off(r, c)) = src[i];
        }
    }
    __syncthreads();
    FENCE_PROXY_ASYNC();

    const uint32_t A_s = ab + OFF_A;
    const uint32_t Bs_[2] = { ab + OFF_B0, ab + OFF_B1 };
    const char* tb = (const char*)g_ubsw + ((size_t)sp * NTILES << 15);

    if (t == 0) {
        MBARRIER_EXPECT_TX(MB,     32768u); bulk_ld(Bs_[0], tb,         32768u, MB);
        MBARRIER_EXPECT_TX(MB + 8, 32768u); bulk_ld(Bs_[1], tb + 32768, 32768u, MB + 8);
    }

    // precomputed ldsm addresses (vary only in chunk per k)
    const int a_row0 = m0w + (lane & 15);
    const int b_row0 = n0w + (lane & 7) + ((lane >> 4) << 3);
    const int a_chsel = (lane >> 4);
    const int b_chsel = ((lane >> 3) & 1);

    int ph[2] = {0, 0};
    for (int i = 0; i < NTILES; i++) {
        const int s = i & 1;
        const uint32_t Bs = Bs_[s];
        MBARRIER_WAIT_PARITY(MB + s * 8, ph[s]); ph[s] ^= 1;

        // ---- MMA: warp tile 32 rows x 32 cols, f16 accum ----
        uint32_t acc[2][4][2];
        #pragma unroll
        for (int mi = 0; mi < 2; mi++)
            #pragma unroll
            for (int nf = 0; nf < 4; nf++) { acc[mi][nf][0] = 0u; acc[mi][nf][1] = 0u; }

        #pragma unroll
        for (int k = 0; k < 8; k++) {
            uint32_t af[2][4], bf[2][4];
            ldsm_x4(A_s + tile_off(a_row0,      2 * k + a_chsel), af[0]);
            ldsm_x4(A_s + tile_off(a_row0 + 16, 2 * k + a_chsel), af[1]);
            ldsm_x4(Bs  + tile_off(b_row0,      2 * k + b_chsel), bf[0]);
            ldsm_x4(Bs  + tile_off(b_row0 + 16, 2 * k + b_chsel), bf[1]);
            #pragma unroll
            for (int nf4 = 0; nf4 < 2; nf4++) {
                mma_f16(acc[0][nf4 * 2 + 0], af[0], bf[nf4][0], bf[nf4][1]);
                mma_f16(acc[1][nf4 * 2 + 0], af[1], bf[nf4][0], bf[nf4][1]);
                mma_f16(acc[0][nf4 * 2 + 1], af[0], bf[nf4][2], bf[nf4][3]);
                mma_f16(acc[1][nf4 * 2 + 1], af[1], bf[nf4][2], bf[nf4][3]);
            }
        }

        // ---- per-row max (over this warp's 32 cols) + threshold trig ----
        #pragma unroll
        for (int mi = 0; mi < 2; mi++)
            #pragma unroll
            for (int h = 0; h < 2; h++) {
                __half2 m2 = *(__half2*)&acc[mi][0][h];
                #pragma unroll
                for (int nf = 1; nf < 4; nf++)
                    m2 = __hmax2(m2, *(__half2*)&acc[mi][nf][h]);
                float mx = fmaxf(__low2float(m2), __high2float(m2));
                mx = fmaxf(mx, __shfl_xor_sync(0xffffffffu, mx, 1));
                mx = fmaxf(mx, __shfl_xor_sync(0xffffffffu, mx, 2));
                int row = m0w + mi * 16 + (lane >> 2) + h * 8;
                if ((lane & 3) == 0 && mx > thr[row]) trig[row] = 1;   // benign race
            }
        __syncthreads();   // trig visible; B[s] fully consumed

        // ---- spill triggered bands (each warp: its 32-col slice) ----
        {
            int f = trig[m0w + lane];
            unsigned bal = __ballot_sync(0xffffffffu, f != 0);
            if (bal) {
                #pragma unroll
                for (int mi = 0; mi < 2; mi++) {
                    int row = m0w + mi * 16 + (lane >> 2);
                    #pragma unroll
                    for (int nf = 0; nf < 4; nf++) {
                        int cp = wc * 16 + nf * 4 + (lane & 3);
                        simsu[row * SP_U32 + cp]       = acc[mi][nf][0];
                        simsu[(row + 8) * SP_U32 + cp] = acc[mi][nf][1];
                    }
                }
            }
        }
        if (t == 0 && i + 2 < NTILES) {
            MBARRIER_EXPECT_TX(MB + s * 8, 32768u);
            bulk_ld(Bs, tb + ((size_t)(i + 2) << 15), 32768u, MB + s * 8);
        }
        __syncthreads();   // sims visible

        // ---- owner threads (t<128) scan triggered rows ----
        if (t < TM && trig[t]) {
            int nvalid = min(TN, NPS - i * TN);
            int cbase = u0 + i * TN;
            const uint32_t* srow = simsu + t * SP_U32;
            for (int cp = 0; cp * 2 < nvalid; cp++) {
                uint32_t pk = srow[cp];
                __half2 hv = *(__half2*)&pk;
                #pragma unroll
                for (int hh = 0; hh < 2; hh++) {
                    int col = cp * 2 + hh;
                    if (col >= nvalid) break;
                    float v = hh ? __high2float(hv) : __low2float(hv);
                    int idx = cbase + col;
                    if (v > topv[CAND - 1] ||
                        (v == topv[CAND - 1] && idx < topi[CAND - 1])) {
                        float vv = v; int ii = idx;
                        #pragma unroll
                        for (int p = 0; p < CAND; p++) {
                            bool better = (vv > topv[p]) || (vv == topv[p] && ii < topi[p]);
                            if (better) {
                                float tv = topv[p]; topv[p] = vv; vv = tv;
                                int   ti = topi[p]; topi[p] = ii; ii = ti;
                            }
                        }
                    }
                }
            }
            thr[t] = topv[CAND - 1];
            trig[t] = 0;
        }
        __syncthreads();
    }

    if (t < TM) {
        size_t b = (size_t)(q0 + t) * NCAND + sp * CAND;
        #pragma unroll
        for (int e = 0; e < CAND; e++) g_ci[b + e] = topi[e];
    }
}

// ---------------- Kernel C: exact rescore + select + gather -----------------
__global__ void finalize_kernel(float* __restrict__ out) {
    __shared__ float cv[NCAND];
    __shared__ int   ci[NCAND];
    __shared__ int   sel[TOPK];
    __shared__ float selv[TOPK];

    const int q = blockIdx.x;
    const int t = threadIdx.x;
    const int w = t >> 5, lane = t & 31;

    if (t < NCAND) ci[t] = g_ci[(size_t)q * NCAND + t];
    __syncthreads();

    float4 qv = *(const float4*)(g_q_n + (size_t)q * DIM + lane * 4);
    #pragma unroll 1
    for (int cc = 0; cc < 8; cc++) {
        int idx = ci[w * 8 + cc];
        float4 uv = *(const float4*)(g_ue_n + (size_t)idx * DIM + lane * 4);
        float s = qv.x * uv.x;
        s = fmaf(qv.y, uv.y, s);
        s = fmaf(qv.z, uv.z, s);
        s = fmaf(qv.w, uv.w, s);
        #pragma unroll
        for (int o = 16; o > 0; o >>= 1) s += __shfl_xor_sync(0xffffffffu, s, o);
        if (lane == 0) cv[w * 8 + cc] = s;
    }
    __syncthreads();

    if (t == 0) {
        float bv[K1]; int bi[K1]; int cnt = 0;
        for (int i = 0; i < NCAND; i++) {
            float v = cv[i]; int id = ci[i];
            bool better = (cnt < K1) || (v > bv[K1 - 1]) || (v == bv[K1 - 1] && id < bi[K1 - 1]);
            if (!better) continue;
            int j = (cnt < K1) ? cnt : K1 - 1;
            while (j > 0 && (v > bv[j - 1] || (v == bv[j - 1] && id < bi[j - 1]))) {
                bv[j] = bv[j - 1]; bi[j] = bi[j - 1]; j--;
            }
            bv[j] = v; bi[j] = id;
            if (cnt < K1) cnt++;
        }
        int order[K1]; int nv = 0;
        for (int i = 0; i < K1; i++) if (bv[i] < 0.9999f) order[nv++] = i;
        int oi = nv;
        for (int i = 0; i < K1; i++) if (!(bv[i] < 0.9999f)) order[oi++] = i;
        for (int j = 0; j < TOPK; j++) {
            int pos = (nv > 0) ? order[min(j, nv - 1)] : j;
            sel[j] = bi[pos]; selv[j] = bv[pos];
        }
    }
    __syncthreads();

    float* oute = out;
    float* outs = out + (size_t)BQ * TOPK * DIM;
    #pragma unroll
    for (int j = 0; j < TOPK; j++)
        oute[((size_t)q * TOPK + j) * DIM + t] = g_ue_n[(size_t)sel[j] * DIM + t];
    if (t < TOPK) outs[(size_t)q * TOPK + t] = selv[t];
}

// ---------------- launch ----------------------------------------------------
extern "C" void kernel_launch(void* const* d_in, const int* in_sizes, int n_in,
                              void* d_out, int out_size) {
    const float* q = (const float*)d_in[0];
    const float* u = (const float*)d_in[1];
    if (n_in >= 2 && in_sizes[0] != BQ * DIM) { const float* tmp = q; q = u; u = tmp; }
    float* out = (float*)d_out;

    int rows = NU + BQ + NSPLIT * PADROWS;
    prep_kernel<<<(rows + 7) / 8, 256>>>(q, u);

    cudaFuncSetAttribute(cand_kernel, cudaFuncAttributeMaxDynamicSharedMemorySize, SMEM_BYTES);
    cand_kernel<<<dim3(QB, NSPLIT), 512, SMEM_BYTES>>>();

    finalize_kernel<<<BQ, DIM>>>(out);
}